// round 13
// baseline (speedup 1.0000x reference)
#include <cuda_runtime.h>
#include <cuda_fp16.h>
#include <cuda_bf16.h>

#define DD 96
#define HH 128
#define WW 160
#define NPTS (DD*HH*WW)          // 1,966,080
#define PBLK 256                 // prep block
#define PGRID 1216               // prep persistent grid (152 SMs * 8)
#define BLK 128                  // warp kernel block
#define PPT 2                    // points per thread (strided by BLK)
#define PPB (BLK*PPT)            // 256 points per block
// warp grid = NPTS/PPB = 7680 blocks

// fp16 2x2 (y,x) corner-patch table, one entry per (z,y,x):
//   .x = half2(v[z,y ,x ])   .y = half2(v[z,y ,x1])
//   .z = half2(v[z,y1,x ])   .w = half2(v[z,y1,x1])   (x1,y1 border-clamped)
__device__ uint4 g_patch[NPTS];

static __device__ __forceinline__ unsigned packh2(float2 v) {
    __half2 h = __float22half2_rn(v);
    return *reinterpret_cast<unsigned*>(&h);
}

// ---------------------------------------------------------------------------
// Prep: persistent grid-stride (measured ~5.7us, near write-BW floor)
__global__ __launch_bounds__(PBLK) void nse_prep_kernel(
    const float* __restrict__ src)
{
    const float2* __restrict__ v2 = (const float2*)src;
    for (int m = blockIdx.x * PBLK + threadIdx.x; m < NPTS; m += PGRID * PBLK) {
        unsigned r = (unsigned)m / 160u;
        unsigned x = (unsigned)m - r * 160u;
        unsigned y = r & 127u;

        const int mx  = (x < WW - 1) ? m + 1  : m;
        const int my  = (y < HH - 1) ? m + WW : m;
        const int mxy = (x < WW - 1) ? my + 1 : my;

        float2 a = __ldg(&v2[m]);
        float2 b = __ldg(&v2[mx]);
        float2 c = __ldg(&v2[my]);
        float2 d = __ldg(&v2[mxy]);

        uint4 o;
        o.x = packh2(a); o.y = packh2(b); o.z = packh2(c); o.w = packh2(d);
        g_patch[m] = o;
    }
}

// ---------------------------------------------------------------------------
// Warp: BLK=128, 16 blocks/SM (regs<=32), strided PPT=2,
// per-point pipeline (math -> gathers(.cg) -> independent stores),
// gathers bypass L1 allocation (no reuse; avoids 128B line fills).
__global__ __launch_bounds__(BLK, 16) void nse_warp_kernel(
    const float* __restrict__ flow,   // (N,7): t(3), qv(3), qw(1)
    float* __restrict__ out)          // [warped 2N | new_loc 3N | grid 3N]
{
    __shared__ float sflow[PPB * 7];  // 7168 B

    const int tid = threadIdx.x;
    const int n0  = blockIdx.x * PPB;

    // Coalesced stage of this block's 256 flow rows (streaming).
    const float* fsrc = flow + (size_t)n0 * 7;
    #pragma unroll
    for (int i = 0; i < 7 * PPT; ++i)
        sflow[tid + i * BLK] = __ldcs(&fsrc[tid + i * BLK]);
    __syncthreads();

    float wxv[PPT], wyv[PPT], wzv[PPT];
    uint4 P0[PPT], P1[PPT];

    // Per-point pipeline: math -> issue gathers -> drain independent stores.
    #pragma unroll
    for (int p = 0; p < PPT; ++p) {
        const int n = n0 + p * BLK + tid;     // strided: all stores coalesced

        unsigned r = (unsigned)n / 160u;
        unsigned k = (unsigned)n - r * 160u;
        unsigned j = r & 127u;
        unsigned i = r >> 7;

        const float inv_mx = 1.0f / 159.0f;
        float gx = (2.0f * (float)i -  95.0f) * inv_mx;
        float gy = (2.0f * (float)j - 127.0f) * inv_mx;
        float gz = (2.0f * (float)k - 159.0f) * inv_mx;

        // bank = 7*tid mod 32, gcd(7,32)=1 -> conflict-free scalar LDS
        const float* f = &sflow[(p * BLK + tid) * 7];
        float tx = f[0], ty = f[1], tz = f[2];
        float qx = f[3], qy = f[4], qz = f[5], qw = f[6];

        float uvx = qy * gz - qz * gy + qw * gx;
        float uvy = qz * gx - qx * gz + qw * gy;
        float uvz = qx * gy - qy * gx + qw * gz;
        float Rx = gx + 2.0f * (qy * uvz - qz * uvy) + tx;
        float Ry = gy + 2.0f * (qz * uvx - qx * uvz) + ty;
        float Rz = gz + 2.0f * (qx * uvy - qy * uvx) + tz;

        float ix = fminf(fmaxf(0.5f * (Rz * 159.0f + 159.0f), 0.0f), 159.0f);
        float iy = fminf(fmaxf(0.5f * (Ry * 159.0f + 127.0f), 0.0f), 127.0f);
        float iz = fminf(fmaxf(0.5f * (Rx * 159.0f +  95.0f), 0.0f),  95.0f);

        int x0 = (int)ix, y0 = (int)iy, z0 = (int)iz;
        int z1 = min(z0 + 1, DD - 1);

        wxv[p] = ix - (float)x0;
        wyv[p] = iy - (float)y0;
        wzv[p] = iz - (float)z0;

        int base = y0 * WW + x0;

        // Issue this point's gathers immediately (L2-only, no L1 fill).
        P0[p] = __ldcg(&g_patch[z0 * (HH * WW) + base]);
        P1[p] = __ldcg(&g_patch[z1 * (HH * WW) + base]);

        // Gather-independent streams while the loads are in flight.
        __stcs(&out[2 * NPTS + n], Rx);
        __stcs(&out[3 * NPTS + n], Ry);
        __stcs(&out[4 * NPTS + n], Rz);
        __stcs(&out[5 * NPTS + n], gx);
        __stcs(&out[6 * NPTS + n], gy);
        __stcs(&out[7 * NPTS + n], gz);
    }

    // Blend and store warped (coalesced scalar stores).
    #pragma unroll
    for (int p = 0; p < PPT; ++p) {
        const int n = n0 + p * BLK + tid;
        float wx = wxv[p], wy = wyv[p], wz = wzv[p];
        float ux = 1.0f - wx, uy = 1.0f - wy, uz = 1.0f - wz;

        float2 a0 = __half22float2(*reinterpret_cast<const __half2*>(&P0[p].x));
        float2 b0 = __half22float2(*reinterpret_cast<const __half2*>(&P0[p].y));
        float2 c0 = __half22float2(*reinterpret_cast<const __half2*>(&P0[p].z));
        float2 d0 = __half22float2(*reinterpret_cast<const __half2*>(&P0[p].w));
        float s0x = (a0.x * ux + b0.x * wx) * uy + (c0.x * ux + d0.x * wx) * wy;
        float s0y = (a0.y * ux + b0.y * wx) * uy + (c0.y * ux + d0.y * wx) * wy;

        float2 a1 = __half22float2(*reinterpret_cast<const __half2*>(&P1[p].x));
        float2 b1 = __half22float2(*reinterpret_cast<const __half2*>(&P1[p].y));
        float2 c1 = __half22float2(*reinterpret_cast<const __half2*>(&P1[p].z));
        float2 d1 = __half22float2(*reinterpret_cast<const __half2*>(&P1[p].w));
        float s1x = (a1.x * ux + b1.x * wx) * uy + (c1.x * ux + d1.x * wx) * wy;
        float s1y = (a1.y * ux + b1.y * wx) * uy + (c1.y * ux + d1.y * wx) * wy;

        __stcs(&out[n],        s0x * uz + s1x * wz);
        __stcs(&out[NPTS + n], s0y * uz + s1y * wz);
    }
}

extern "C" void kernel_launch(void* const* d_in, const int* in_sizes, int n_in,
                              void* d_out, int out_size) {
    const float* src  = (const float*)d_in[0];
    const float* flow = (const float*)d_in[1];
    if (n_in >= 2 && in_sizes[0] == 7 * NPTS && in_sizes[1] == 2 * NPTS) {
        src  = (const float*)d_in[1];
        flow = (const float*)d_in[0];
    }
    float* out = (float*)d_out;
    nse_prep_kernel<<<PGRID, PBLK>>>(src);
    nse_warp_kernel<<<NPTS / PPB, BLK>>>(flow, out);
}

// round 14
// speedup vs baseline: 1.3374x; 1.3374x over previous
#include <cuda_runtime.h>
#include <cuda_fp16.h>
#include <cuda_bf16.h>

#define DD 96
#define HH 128
#define WW 160
#define HW (HH*WW)
#define NPTS (DD*HH*WW)          // 1,966,080
#define PBLK 256                 // prep block
#define PGRID 1216               // prep persistent grid (152 SMs * 8)
#define BLK 128                  // warp kernel block
#define PPT 2                    // points per thread
#define PPB (BLK*PPT)            // 256 points per block
// warp grid = NPTS/PPB = 7680 blocks

// fp16 2x2 (y,x) corner-patch table, z-interleaved layout:
//   entry e(z,y,x) = (((z>>1)*HW + y*WW + x) << 1) | (z & 1)
// so (z even, z+1) pairs are adjacent 16B entries inside one 32B sector ->
// the warp kernel's second gather MSHR-merges with the first.
//   .x = half2(v[z,y ,x ])   .y = half2(v[z,y ,x1])
//   .z = half2(v[z,y1,x ])   .w = half2(v[z,y1,x1])   (x1,y1 border-clamped)
__device__ uint4 g_patch[NPTS];

static __device__ __forceinline__ unsigned packh2(float2 v) {
    __half2 h = __float22half2_rn(v);
    return *reinterpret_cast<unsigned*>(&h);
}

static __device__ __forceinline__ int patch_idx(int z, int yx_base) {
    return (((z >> 1) * HW + yx_base) << 1) | (z & 1);
}

// ---------------------------------------------------------------------------
// Prep: persistent grid-stride; coalesced reads, near-coalesced (stride-2) writes.
__global__ __launch_bounds__(PBLK) void nse_prep_kernel(
    const float* __restrict__ src)
{
    const float2* __restrict__ v2 = (const float2*)src;
    for (int m = blockIdx.x * PBLK + threadIdx.x; m < NPTS; m += PGRID * PBLK) {
        unsigned r = (unsigned)m / 160u;
        unsigned x = (unsigned)m - r * 160u;
        unsigned y = r & 127u;
        unsigned z = r >> 7;

        const int mx  = (x < WW - 1) ? m + 1  : m;
        const int my  = (y < HH - 1) ? m + WW : m;
        const int mxy = (x < WW - 1) ? my + 1 : my;

        float2 a = __ldg(&v2[m]);
        float2 b = __ldg(&v2[mx]);
        float2 c = __ldg(&v2[my]);
        float2 d = __ldg(&v2[mxy]);

        uint4 o;
        o.x = packh2(a); o.y = packh2(b); o.z = packh2(c); o.w = packh2(d);
        g_patch[patch_idx((int)z, (int)(y * WW + x))] = o;
    }
}

// ---------------------------------------------------------------------------
// Warp: R11 config (BLK=128, 16 blocks/SM, PPT=2 consecutive, __ldg gathers,
// float2 streaming stores) + z-interleaved table indexing.
__global__ __launch_bounds__(BLK, 16) void nse_warp_kernel(
    const float* __restrict__ flow,   // (N,7): t(3), qv(3), qw(1)
    float* __restrict__ out)          // [warped 2N | new_loc 3N | grid 3N]
{
    __shared__ float sflow[PPB * 7];  // 7168 B

    const int tid = threadIdx.x;
    const int n0  = blockIdx.x * PPB;

    // Coalesced stage of this block's 256 flow rows (streaming).
    const float* fsrc = flow + (size_t)n0 * 7;
    #pragma unroll
    for (int i = 0; i < 7 * PPT; ++i)
        sflow[tid + i * BLK] = __ldcs(&fsrc[tid + i * BLK]);
    __syncthreads();

    const int nA = n0 + 2 * tid;      // this thread: points nA, nA+1

    float rx[PPT], ry[PPT], rz[PPT];
    float gxv[PPT], gyv[PPT], gzv[PPT];
    float wxv[PPT], wyv[PPT], wzv[PPT];
    int   m0[PPT], m1[PPT];

    #pragma unroll
    for (int p = 0; p < PPT; ++p) {
        const int n = nA + p;

        unsigned r = (unsigned)n / 160u;
        unsigned k = (unsigned)n - r * 160u;
        unsigned j = r & 127u;
        unsigned i = r >> 7;

        const float inv_mx = 1.0f / 159.0f;
        float gx = (2.0f * (float)i -  95.0f) * inv_mx;
        float gy = (2.0f * (float)j - 127.0f) * inv_mx;
        float gz = (2.0f * (float)k - 159.0f) * inv_mx;

        const float* f = &sflow[(2 * tid + p) * 7];
        float tx = f[0], ty = f[1], tz = f[2];
        float qx = f[3], qy = f[4], qz = f[5], qw = f[6];

        float uvx = qy * gz - qz * gy + qw * gx;
        float uvy = qz * gx - qx * gz + qw * gy;
        float uvz = qx * gy - qy * gx + qw * gz;
        float Rx = gx + 2.0f * (qy * uvz - qz * uvy) + tx;
        float Ry = gy + 2.0f * (qz * uvx - qx * uvz) + ty;
        float Rz = gz + 2.0f * (qx * uvy - qy * uvx) + tz;

        float ix = fminf(fmaxf(0.5f * (Rz * 159.0f + 159.0f), 0.0f), 159.0f);
        float iy = fminf(fmaxf(0.5f * (Ry * 159.0f + 127.0f), 0.0f), 127.0f);
        float iz = fminf(fmaxf(0.5f * (Rx * 159.0f +  95.0f), 0.0f),  95.0f);

        int x0 = (int)ix, y0 = (int)iy, z0 = (int)iz;
        int z1 = min(z0 + 1, DD - 1);

        wxv[p] = ix - (float)x0;
        wyv[p] = iy - (float)y0;
        wzv[p] = iz - (float)z0;
        rx[p] = Rx; ry[p] = Ry; rz[p] = Rz;
        gxv[p] = gx; gyv[p] = gy; gzv[p] = gz;

        int base = y0 * WW + x0;
        m0[p] = patch_idx(z0, base);
        m1[p] = patch_idx(z1, base);
    }

    // Issue all 4 gathers; z-pairs adjacent in memory MSHR-merge (even z0).
    uint4 P0[PPT], P1[PPT];
    #pragma unroll
    for (int p = 0; p < PPT; ++p) {
        P0[p] = __ldg(&g_patch[m0[p]]);
        P1[p] = __ldg(&g_patch[m1[p]]);
    }

    // Gather-independent output streams while loads are in flight.
    float2* __restrict__ o2 = (float2*)out;
    const int h = nA >> 1;                      // float2 index
    __stcs(&o2[(2*NPTS >> 1) + h], make_float2(rx[0], rx[1]));
    __stcs(&o2[(3*NPTS >> 1) + h], make_float2(ry[0], ry[1]));
    __stcs(&o2[(4*NPTS >> 1) + h], make_float2(rz[0], rz[1]));
    __stcs(&o2[(5*NPTS >> 1) + h], make_float2(gxv[0], gxv[1]));
    __stcs(&o2[(6*NPTS >> 1) + h], make_float2(gyv[0], gyv[1]));
    __stcs(&o2[(7*NPTS >> 1) + h], make_float2(gzv[0], gzv[1]));

    float o0[PPT], o1[PPT];
    #pragma unroll
    for (int p = 0; p < PPT; ++p) {
        float wx = wxv[p], wy = wyv[p], wz = wzv[p];
        float ux = 1.0f - wx, uy = 1.0f - wy, uz = 1.0f - wz;

        float2 a0 = __half22float2(*reinterpret_cast<const __half2*>(&P0[p].x));
        float2 b0 = __half22float2(*reinterpret_cast<const __half2*>(&P0[p].y));
        float2 c0 = __half22float2(*reinterpret_cast<const __half2*>(&P0[p].z));
        float2 d0 = __half22float2(*reinterpret_cast<const __half2*>(&P0[p].w));
        float s0x = (a0.x * ux + b0.x * wx) * uy + (c0.x * ux + d0.x * wx) * wy;
        float s0y = (a0.y * ux + b0.y * wx) * uy + (c0.y * ux + d0.y * wx) * wy;

        float2 a1 = __half22float2(*reinterpret_cast<const __half2*>(&P1[p].x));
        float2 b1 = __half22float2(*reinterpret_cast<const __half2*>(&P1[p].y));
        float2 c1 = __half22float2(*reinterpret_cast<const __half2*>(&P1[p].z));
        float2 d1 = __half22float2(*reinterpret_cast<const __half2*>(&P1[p].w));
        float s1x = (a1.x * ux + b1.x * wx) * uy + (c1.x * ux + d1.x * wx) * wy;
        float s1y = (a1.y * ux + b1.y * wx) * uy + (c1.y * ux + d1.y * wx) * wy;

        o0[p] = s0x * uz + s1x * wz;
        o1[p] = s0y * uz + s1y * wz;
    }

    __stcs(&o2[h],               make_float2(o0[0], o0[1]));
    __stcs(&o2[(NPTS >> 1) + h], make_float2(o1[0], o1[1]));
}

extern "C" void kernel_launch(void* const* d_in, const int* in_sizes, int n_in,
                              void* d_out, int out_size) {
    const float* src  = (const float*)d_in[0];
    const float* flow = (const float*)d_in[1];
    if (n_in >= 2 && in_sizes[0] == 7 * NPTS && in_sizes[1] == 2 * NPTS) {
        src  = (const float*)d_in[1];
        flow = (const float*)d_in[0];
    }
    float* out = (float*)d_out;
    nse_prep_kernel<<<PGRID, PBLK>>>(src);
    nse_warp_kernel<<<NPTS / PPB, BLK>>>(flow, out);
}

// round 15
// speedup vs baseline: 1.4932x; 1.1164x over previous
#include <cuda_runtime.h>
#include <cuda_fp16.h>
#include <cuda_bf16.h>

#define DD 96
#define HH 128
#define WW 160
#define HW (HH*WW)
#define NPTS (DD*HH*WW)          // 1,966,080
#define PBLK 256                 // prep block
#define PGRID 1216               // prep persistent grid (152 SMs * 8)
#define BLK 128                  // warp kernel block
#define PPT 2                    // points per thread
#define PPB (BLK*PPT)            // 256 points per block
// warp grid = NPTS/PPB = 7680 blocks

// fp16 2x2 (y,x) corner-patch table, z-interleaved layout:
//   entry e(z,y,x) = (((z>>1)*HW + y*WW + x) << 1) | (z & 1)
// so (z even, z+1) pairs are adjacent 16B entries inside one 32B sector ->
// the warp kernel's second gather MSHR-merges with the first.
//   .x = half2(v[z,y ,x ])   .y = half2(v[z,y ,x1])
//   .z = half2(v[z,y1,x ])   .w = half2(v[z,y1,x1])   (x1,y1 border-clamped)
__device__ uint4 g_patch[NPTS];

static __device__ __forceinline__ unsigned packh2(float2 v) {
    __half2 h = __float22half2_rn(v);
    return *reinterpret_cast<unsigned*>(&h);
}

static __device__ __forceinline__ int patch_idx(int z, int yx_base) {
    return (((z >> 1) * HW + yx_base) << 1) | (z & 1);
}

// ---------------------------------------------------------------------------
// Prep: iterate in ENTRY order so stores are fully coalesced; decode (z,y,x)
// from the entry index. Reads split across z-plane pairs at 16-lane
// granularity (still sector-dense); writes are the dominant traffic.
__global__ __launch_bounds__(PBLK) void nse_prep_kernel(
    const float* __restrict__ src)
{
    const float2* __restrict__ v2 = (const float2*)src;
    for (int e = blockIdx.x * PBLK + threadIdx.x; e < NPTS; e += PGRID * PBLK) {
        unsigned s    = (unsigned)e >> 1;
        unsigned zpar = (unsigned)e & 1u;
        unsigned z2   = s / (unsigned)HW;          // const-divisor mul.hi
        unsigned rem  = s - z2 * (unsigned)HW;
        unsigned y    = rem / 160u;
        unsigned x    = rem - y * 160u;
        unsigned z    = 2u * z2 + zpar;            // < 96 always

        const int m   = (int)(z * (unsigned)HW + rem);
        const int mx  = (x < WW - 1) ? m + 1  : m;
        const int my  = (y < HH - 1) ? m + WW : m;
        const int mxy = (x < WW - 1) ? my + 1 : my;

        float2 a = __ldg(&v2[m]);
        float2 b = __ldg(&v2[mx]);
        float2 c = __ldg(&v2[my]);
        float2 d = __ldg(&v2[mxy]);

        uint4 o;
        o.x = packh2(a); o.y = packh2(b); o.z = packh2(c); o.w = packh2(d);
        g_patch[e] = o;                            // coalesced
    }
}

// ---------------------------------------------------------------------------
// Warp: R14 body unchanged (measured 28.8us): BLK=128, 16 blocks/SM, PPT=2,
// __ldg gathers on z-interleaved table, float2 streaming stores.
__global__ __launch_bounds__(BLK, 16) void nse_warp_kernel(
    const float* __restrict__ flow,   // (N,7): t(3), qv(3), qw(1)
    float* __restrict__ out)          // [warped 2N | new_loc 3N | grid 3N]
{
    __shared__ float sflow[PPB * 7];  // 7168 B

    const int tid = threadIdx.x;
    const int n0  = blockIdx.x * PPB;

    // Coalesced stage of this block's 256 flow rows (streaming).
    const float* fsrc = flow + (size_t)n0 * 7;
    #pragma unroll
    for (int i = 0; i < 7 * PPT; ++i)
        sflow[tid + i * BLK] = __ldcs(&fsrc[tid + i * BLK]);
    __syncthreads();

    const int nA = n0 + 2 * tid;      // this thread: points nA, nA+1

    float rx[PPT], ry[PPT], rz[PPT];
    float gxv[PPT], gyv[PPT], gzv[PPT];
    float wxv[PPT], wyv[PPT], wzv[PPT];
    int   m0[PPT], m1[PPT];

    #pragma unroll
    for (int p = 0; p < PPT; ++p) {
        const int n = nA + p;

        unsigned r = (unsigned)n / 160u;
        unsigned k = (unsigned)n - r * 160u;
        unsigned j = r & 127u;
        unsigned i = r >> 7;

        const float inv_mx = 1.0f / 159.0f;
        float gx = (2.0f * (float)i -  95.0f) * inv_mx;
        float gy = (2.0f * (float)j - 127.0f) * inv_mx;
        float gz = (2.0f * (float)k - 159.0f) * inv_mx;

        const float* f = &sflow[(2 * tid + p) * 7];
        float tx = f[0], ty = f[1], tz = f[2];
        float qx = f[3], qy = f[4], qz = f[5], qw = f[6];

        float uvx = qy * gz - qz * gy + qw * gx;
        float uvy = qz * gx - qx * gz + qw * gy;
        float uvz = qx * gy - qy * gx + qw * gz;
        float Rx = gx + 2.0f * (qy * uvz - qz * uvy) + tx;
        float Ry = gy + 2.0f * (qz * uvx - qx * uvz) + ty;
        float Rz = gz + 2.0f * (qx * uvy - qy * uvx) + tz;

        float ix = fminf(fmaxf(0.5f * (Rz * 159.0f + 159.0f), 0.0f), 159.0f);
        float iy = fminf(fmaxf(0.5f * (Ry * 159.0f + 127.0f), 0.0f), 127.0f);
        float iz = fminf(fmaxf(0.5f * (Rx * 159.0f +  95.0f), 0.0f),  95.0f);

        int x0 = (int)ix, y0 = (int)iy, z0 = (int)iz;
        int z1 = min(z0 + 1, DD - 1);

        wxv[p] = ix - (float)x0;
        wyv[p] = iy - (float)y0;
        wzv[p] = iz - (float)z0;
        rx[p] = Rx; ry[p] = Ry; rz[p] = Rz;
        gxv[p] = gx; gyv[p] = gy; gzv[p] = gz;

        int base = y0 * WW + x0;
        m0[p] = patch_idx(z0, base);
        m1[p] = patch_idx(z1, base);
    }

    // Issue all 4 gathers; z-pairs adjacent in memory MSHR-merge (even z0).
    uint4 P0[PPT], P1[PPT];
    #pragma unroll
    for (int p = 0; p < PPT; ++p) {
        P0[p] = __ldg(&g_patch[m0[p]]);
        P1[p] = __ldg(&g_patch[m1[p]]);
    }

    // Gather-independent output streams while loads are in flight.
    float2* __restrict__ o2 = (float2*)out;
    const int h = nA >> 1;                      // float2 index
    __stcs(&o2[(2*NPTS >> 1) + h], make_float2(rx[0], rx[1]));
    __stcs(&o2[(3*NPTS >> 1) + h], make_float2(ry[0], ry[1]));
    __stcs(&o2[(4*NPTS >> 1) + h], make_float2(rz[0], rz[1]));
    __stcs(&o2[(5*NPTS >> 1) + h], make_float2(gxv[0], gxv[1]));
    __stcs(&o2[(6*NPTS >> 1) + h], make_float2(gyv[0], gyv[1]));
    __stcs(&o2[(7*NPTS >> 1) + h], make_float2(gzv[0], gzv[1]));

    float o0[PPT], o1[PPT];
    #pragma unroll
    for (int p = 0; p < PPT; ++p) {
        float wx = wxv[p], wy = wyv[p], wz = wzv[p];
        float ux = 1.0f - wx, uy = 1.0f - wy, uz = 1.0f - wz;

        float2 a0 = __half22float2(*reinterpret_cast<const __half2*>(&P0[p].x));
        float2 b0 = __half22float2(*reinterpret_cast<const __half2*>(&P0[p].y));
        float2 c0 = __half22float2(*reinterpret_cast<const __half2*>(&P0[p].z));
        float2 d0 = __half22float2(*reinterpret_cast<const __half2*>(&P0[p].w));
        float s0x = (a0.x * ux + b0.x * wx) * uy + (c0.x * ux + d0.x * wx) * wy;
        float s0y = (a0.y * ux + b0.y * wx) * uy + (c0.y * ux + d0.y * wx) * wy;

        float2 a1 = __half22float2(*reinterpret_cast<const __half2*>(&P1[p].x));
        float2 b1 = __half22float2(*reinterpret_cast<const __half2*>(&P1[p].y));
        float2 c1 = __half22float2(*reinterpret_cast<const __half2*>(&P1[p].z));
        float2 d1 = __half22float2(*reinterpret_cast<const __half2*>(&P1[p].w));
        float s1x = (a1.x * ux + b1.x * wx) * uy + (c1.x * ux + d1.x * wx) * wy;
        float s1y = (a1.y * ux + b1.y * wx) * uy + (c1.y * ux + d1.y * wx) * wy;

        o0[p] = s0x * uz + s1x * wz;
        o1[p] = s0y * uz + s1y * wz;
    }

    __stcs(&o2[h],               make_float2(o0[0], o0[1]));
    __stcs(&o2[(NPTS >> 1) + h], make_float2(o1[0], o1[1]));
}

extern "C" void kernel_launch(void* const* d_in, const int* in_sizes, int n_in,
                              void* d_out, int out_size) {
    const float* src  = (const float*)d_in[0];
    const float* flow = (const float*)d_in[1];
    if (n_in >= 2 && in_sizes[0] == 7 * NPTS && in_sizes[1] == 2 * NPTS) {
        src  = (const float*)d_in[1];
        flow = (const float*)d_in[0];
    }
    float* out = (float*)d_out;
    nse_prep_kernel<<<PGRID, PBLK>>>(src);
    nse_warp_kernel<<<NPTS / PPB, BLK>>>(flow, out);
}

// round 16
// speedup vs baseline: 1.5009x; 1.0052x over previous
#include <cuda_runtime.h>
#include <cuda_fp16.h>
#include <cuda_bf16.h>

#define DD 96
#define HH 128
#define WW 160
#define HW (HH*WW)
#define NPTS (DD*HH*WW)          // 1,966,080
#define NPAIRS (NPTS/2)          // 983,040 z-pair sites
#define PBLK 256                 // prep block
#define PGRID 1216               // prep persistent grid (152 SMs * 8)
#define BLK 128                  // warp kernel block
#define PPT 2                    // points per thread
#define PPB (BLK*PPT)            // 256 points per block
// warp grid = NPTS/PPB = 7680 blocks

// fp16 2x2 (y,x) corner-patch table, z-interleaved layout:
//   entry e(z,y,x) = (((z>>1)*HW + y*WW + x) << 1) | (z & 1)
// so (z even, z+1) pairs are adjacent 16B entries inside one 32B sector ->
// the warp kernel's second gather MSHR-merges with the first (even z0).
//   .x = half2(v[z,y ,x ])   .y = half2(v[z,y ,x1])
//   .z = half2(v[z,y1,x ])   .w = half2(v[z,y1,x1])   (x1,y1 border-clamped)
__device__ uint4 g_patch[NPTS];

static __device__ __forceinline__ unsigned packh2(float2 v) {
    __half2 h = __float22half2_rn(v);
    return *reinterpret_cast<unsigned*>(&h);
}

static __device__ __forceinline__ int patch_idx(int z, int yx_base) {
    return (((z >> 1) * HW + yx_base) << 1) | (z & 1);
}

// ---------------------------------------------------------------------------
// Prep: one thread per z-PAIR site. Loads 2x2 corners from both planes
// (dense warp-wide streams) and writes both 16B entries with ONE 256-bit
// store (32B-aligned, fully coalesced).
__global__ __launch_bounds__(PBLK) void nse_prep_kernel(
    const float* __restrict__ src)
{
    const float2* __restrict__ v2 = (const float2*)src;
    for (int g = blockIdx.x * PBLK + threadIdx.x; g < NPAIRS; g += PGRID * PBLK) {
        unsigned z2  = (unsigned)g / (unsigned)HW;     // const-divisor mul.hi
        unsigned rem = (unsigned)g - z2 * (unsigned)HW;
        unsigned y   = rem / 160u;
        unsigned x   = rem - y * 160u;

        const int m0 = (int)(2u * z2 * (unsigned)HW + rem);  // plane 2*z2
        const int m1 = m0 + HW;                              // plane 2*z2+1 (<96)
        const int dx = (x < WW - 1) ? 1  : 0;
        const int dy = (y < HH - 1) ? WW : 0;

        float2 a0 = __ldg(&v2[m0]);
        float2 b0 = __ldg(&v2[m0 + dx]);
        float2 c0 = __ldg(&v2[m0 + dy]);
        float2 d0 = __ldg(&v2[m0 + dy + dx]);
        float2 a1 = __ldg(&v2[m1]);
        float2 b1 = __ldg(&v2[m1 + dx]);
        float2 c1 = __ldg(&v2[m1 + dy]);
        float2 d1 = __ldg(&v2[m1 + dy + dx]);

        unsigned r0 = packh2(a0), r1 = packh2(b0), r2 = packh2(c0), r3 = packh2(d0);
        unsigned r4 = packh2(a1), r5 = packh2(b1), r6 = packh2(c1), r7 = packh2(d1);

        // 256-bit store: entries 2g (even-z) and 2g+1 (odd-z) in one shot.
        asm volatile(
            "st.global.v8.b32 [%0], {%1, %2, %3, %4, %5, %6, %7, %8};"
            :: "l"(&g_patch[2 * g]),
               "r"(r0), "r"(r1), "r"(r2), "r"(r3),
               "r"(r4), "r"(r5), "r"(r6), "r"(r7)
            : "memory");
    }
}

// ---------------------------------------------------------------------------
// Warp: R15 body unchanged (measured 28.6us): BLK=128, 16 blocks/SM, PPT=2,
// __ldg gathers on z-interleaved table, float2 streaming stores.
__global__ __launch_bounds__(BLK, 16) void nse_warp_kernel(
    const float* __restrict__ flow,   // (N,7): t(3), qv(3), qw(1)
    float* __restrict__ out)          // [warped 2N | new_loc 3N | grid 3N]
{
    __shared__ float sflow[PPB * 7];  // 7168 B

    const int tid = threadIdx.x;
    const int n0  = blockIdx.x * PPB;

    // Coalesced stage of this block's 256 flow rows (streaming).
    const float* fsrc = flow + (size_t)n0 * 7;
    #pragma unroll
    for (int i = 0; i < 7 * PPT; ++i)
        sflow[tid + i * BLK] = __ldcs(&fsrc[tid + i * BLK]);
    __syncthreads();

    const int nA = n0 + 2 * tid;      // this thread: points nA, nA+1

    float rx[PPT], ry[PPT], rz[PPT];
    float gxv[PPT], gyv[PPT], gzv[PPT];
    float wxv[PPT], wyv[PPT], wzv[PPT];
    int   m0[PPT], m1[PPT];

    #pragma unroll
    for (int p = 0; p < PPT; ++p) {
        const int n = nA + p;

        unsigned r = (unsigned)n / 160u;
        unsigned k = (unsigned)n - r * 160u;
        unsigned j = r & 127u;
        unsigned i = r >> 7;

        const float inv_mx = 1.0f / 159.0f;
        float gx = (2.0f * (float)i -  95.0f) * inv_mx;
        float gy = (2.0f * (float)j - 127.0f) * inv_mx;
        float gz = (2.0f * (float)k - 159.0f) * inv_mx;

        const float* f = &sflow[(2 * tid + p) * 7];
        float tx = f[0], ty = f[1], tz = f[2];
        float qx = f[3], qy = f[4], qz = f[5], qw = f[6];

        float uvx = qy * gz - qz * gy + qw * gx;
        float uvy = qz * gx - qx * gz + qw * gy;
        float uvz = qx * gy - qy * gx + qw * gz;
        float Rx = gx + 2.0f * (qy * uvz - qz * uvy) + tx;
        float Ry = gy + 2.0f * (qz * uvx - qx * uvz) + ty;
        float Rz = gz + 2.0f * (qx * uvy - qy * uvx) + tz;

        float ix = fminf(fmaxf(0.5f * (Rz * 159.0f + 159.0f), 0.0f), 159.0f);
        float iy = fminf(fmaxf(0.5f * (Ry * 159.0f + 127.0f), 0.0f), 127.0f);
        float iz = fminf(fmaxf(0.5f * (Rx * 159.0f +  95.0f), 0.0f),  95.0f);

        int x0 = (int)ix, y0 = (int)iy, z0 = (int)iz;
        int z1 = min(z0 + 1, DD - 1);

        wxv[p] = ix - (float)x0;
        wyv[p] = iy - (float)y0;
        wzv[p] = iz - (float)z0;
        rx[p] = Rx; ry[p] = Ry; rz[p] = Rz;
        gxv[p] = gx; gyv[p] = gy; gzv[p] = gz;

        int base = y0 * WW + x0;
        m0[p] = patch_idx(z0, base);
        m1[p] = patch_idx(z1, base);
    }

    // Issue all 4 gathers; z-pairs adjacent in memory MSHR-merge (even z0).
    uint4 P0[PPT], P1[PPT];
    #pragma unroll
    for (int p = 0; p < PPT; ++p) {
        P0[p] = __ldg(&g_patch[m0[p]]);
        P1[p] = __ldg(&g_patch[m1[p]]);
    }

    // Gather-independent output streams while loads are in flight.
    float2* __restrict__ o2 = (float2*)out;
    const int h = nA >> 1;                      // float2 index
    __stcs(&o2[(2*NPTS >> 1) + h], make_float2(rx[0], rx[1]));
    __stcs(&o2[(3*NPTS >> 1) + h], make_float2(ry[0], ry[1]));
    __stcs(&o2[(4*NPTS >> 1) + h], make_float2(rz[0], rz[1]));
    __stcs(&o2[(5*NPTS >> 1) + h], make_float2(gxv[0], gxv[1]));
    __stcs(&o2[(6*NPTS >> 1) + h], make_float2(gyv[0], gyv[1]));
    __stcs(&o2[(7*NPTS >> 1) + h], make_float2(gzv[0], gzv[1]));

    float o0[PPT], o1[PPT];
    #pragma unroll
    for (int p = 0; p < PPT; ++p) {
        float wx = wxv[p], wy = wyv[p], wz = wzv[p];
        float ux = 1.0f - wx, uy = 1.0f - wy, uz = 1.0f - wz;

        float2 a0 = __half22float2(*reinterpret_cast<const __half2*>(&P0[p].x));
        float2 b0 = __half22float2(*reinterpret_cast<const __half2*>(&P0[p].y));
        float2 c0 = __half22float2(*reinterpret_cast<const __half2*>(&P0[p].z));
        float2 d0 = __half22float2(*reinterpret_cast<const __half2*>(&P0[p].w));
        float s0x = (a0.x * ux + b0.x * wx) * uy + (c0.x * ux + d0.x * wx) * wy;
        float s0y = (a0.y * ux + b0.y * wx) * uy + (c0.y * ux + d0.y * wx) * wy;

        float2 a1 = __half22float2(*reinterpret_cast<const __half2*>(&P1[p].x));
        float2 b1 = __half22float2(*reinterpret_cast<const __half2*>(&P1[p].y));
        float2 c1 = __half22float2(*reinterpret_cast<const __half2*>(&P1[p].z));
        float2 d1 = __half22float2(*reinterpret_cast<const __half2*>(&P1[p].w));
        float s1x = (a1.x * ux + b1.x * wx) * uy + (c1.x * ux + d1.x * wx) * wy;
        float s1y = (a1.y * ux + b1.y * wx) * uy + (c1.y * ux + d1.y * wx) * wy;

        o0[p] = s0x * uz + s1x * wz;
        o1[p] = s0y * uz + s1y * wz;
    }

    __stcs(&o2[h],               make_float2(o0[0], o0[1]));
    __stcs(&o2[(NPTS >> 1) + h], make_float2(o1[0], o1[1]));
}

extern "C" void kernel_launch(void* const* d_in, const int* in_sizes, int n_in,
                              void* d_out, int out_size) {
    const float* src  = (const float*)d_in[0];
    const float* flow = (const float*)d_in[1];
    if (n_in >= 2 && in_sizes[0] == 7 * NPTS && in_sizes[1] == 2 * NPTS) {
        src  = (const float*)d_in[1];
        flow = (const float*)d_in[0];
    }
    float* out = (float*)d_out;
    nse_prep_kernel<<<PGRID, PBLK>>>(src);
    nse_warp_kernel<<<NPTS / PPB, BLK>>>(flow, out);
}